// round 4
// baseline (speedup 1.0000x reference)
#include <cuda_runtime.h>

#define TSEQ 2048
#define NTHR 256
#define BT   64

typedef unsigned long long u64;

// ---------------------------------------------------------------------------
// Packed f32x2 helpers (Blackwell). ptxas never auto-fuses FFMA2 from C++;
// it only exists via PTX fma.rn.f32x2.
// ---------------------------------------------------------------------------
__device__ __forceinline__ void ffma2(u64& d, u64 a, u64 b) {
    asm("fma.rn.f32x2 %0, %1, %2, %0;" : "+l"(d) : "l"(a), "l"(b));
}
__device__ __forceinline__ u64 ffma2_o(u64 a, u64 b, u64 c) {
    u64 d; asm("fma.rn.f32x2 %0, %1, %2, %3;" : "=l"(d) : "l"(a), "l"(b), "l"(c));
    return d;
}
__device__ __forceinline__ u64 pack2(float lo, float hi) {
    u64 r; asm("mov.b64 %0, {%1, %2};" : "=l"(r) : "f"(lo), "f"(hi)); return r;
}
__device__ __forceinline__ void unpack2(u64 v, float& lo, float& hi) {
    asm("mov.b64 {%0, %1}, %2;" : "=f"(lo), "=f"(hi) : "l"(v));
}

// Accurate-enough nonlinearities: ex2.approx + rcp.approx (~2 ulp each).
__device__ __forceinline__ float fsig(float x) {
    return __fdividef(1.0f, 1.0f + __expf(-x));
}
__device__ __forceinline__ float ftanh_(float x) {
    x = fminf(fmaxf(x, -15.0f), 15.0f);
    float e = __expf(-2.0f * x);
    return __fdividef(1.0f - e, 1.0f + e);
}

// ---------------------------------------------------------------------------
// SMEM layout (float indices). H=51 padded to HP=52 (padding zeroed).
// Weights interleaved [j][k][gate q=0..3] -> one LDS.128 = packed (i,f),(g,o).
// h stored DUPLICATED as [k][batch][2] -> one LDS.64 = dup'd h operand.
// ---------------------------------------------------------------------------
constexpr int HP = 52;

constexpr int OFF_W1   = 0;                         // [52][52][4]  = 10816
constexpr int OFF_W2   = OFF_W1 + 52 * 52 * 4;      // [52][104][4] = 21632
constexpr int OFF_WXIF = OFF_W2 + 52 * 104 * 4;     // [52][2]
constexpr int OFF_WXGO = OFF_WXIF + 104;
constexpr int OFF_BIF1 = OFF_WXGO + 104;
constexpr int OFF_BGO1 = OFF_BIF1 + 104;
constexpr int OFF_BIF2 = OFF_BGO1 + 104;
constexpr int OFF_BGO2 = OFF_BIF2 + 104;
constexpr int OFF_WLIN = OFF_BGO2 + 104;            // [52]
constexpr int OFF_H1   = OFF_WLIN + 52;             // [52][64][2] = 6656 (even ✓)
constexpr int OFF_H2   = OFF_H1 + 52 * BT * 2;      // 6656
constexpr int OFF_XS   = OFF_H2 + 52 * BT * 2;      // [64][33] = 2112
constexpr int OFF_OS   = OFF_XS + BT * 33;          // 2112
constexpr int OFF_PART = OFF_OS + BT * 33;          // [4][64]
constexpr int SMEM_FLOATS = OFF_PART + 4 * BT;
constexpr int SMEM_BYTES  = SMEM_FLOATS * 4;        // ~203.7 KB

__global__ void __launch_bounds__(NTHR, 1) lstm_f32x2_kernel(
    const float* __restrict__ input,
    const float* __restrict__ W_ih1, const float* __restrict__ W_hh1,
    const float* __restrict__ b_ih1, const float* __restrict__ b_hh1,
    const float* __restrict__ W_ih2, const float* __restrict__ W_hh2,
    const float* __restrict__ b_ih2, const float* __restrict__ b_hh2,
    const float* __restrict__ W_lin, const float* __restrict__ b_lin,
    float* __restrict__ out)
{
    extern __shared__ float sm[];
    const int tid = threadIdx.x;

    // ---- zero everything up to XS (weight padding + h/c state) ----
    for (int i = tid; i < OFF_XS; i += NTHR) sm[i] = 0.0f;
    __syncthreads();

    // ---- stage weights: gate-interleaved [j][k][q] ----
    for (int i = tid; i < 4 * 51 * 51; i += NTHR) {
        int q = i / (51 * 51), rem = i - q * 51 * 51;
        int j = rem / 51, c = rem - j * 51;
        float whh1 = W_hh1[(q * 51 + j) * 51 + c];
        float wih2 = W_ih2[(q * 51 + j) * 51 + c];
        float whh2 = W_hh2[(q * 51 + j) * 51 + c];
        sm[OFF_W1 + j * 208 + c * 4 + q]        = whh1;
        sm[OFF_W2 + j * 416 + c * 4 + q]        = wih2;
        sm[OFF_W2 + j * 416 + (52 + c) * 4 + q] = whh2;
    }
    for (int j = tid; j < 51; j += NTHR) {
        sm[OFF_WXIF + j * 2 + 0] = W_ih1[j];
        sm[OFF_WXIF + j * 2 + 1] = W_ih1[51 + j];
        sm[OFF_WXGO + j * 2 + 0] = W_ih1[102 + j];
        sm[OFF_WXGO + j * 2 + 1] = W_ih1[153 + j];
        sm[OFF_BIF1 + j * 2 + 0] = b_ih1[j]       + b_hh1[j];
        sm[OFF_BIF1 + j * 2 + 1] = b_ih1[51 + j]  + b_hh1[51 + j];
        sm[OFF_BGO1 + j * 2 + 0] = b_ih1[102 + j] + b_hh1[102 + j];
        sm[OFF_BGO1 + j * 2 + 1] = b_ih1[153 + j] + b_hh1[153 + j];
        sm[OFF_BIF2 + j * 2 + 0] = b_ih2[j]       + b_hh2[j];
        sm[OFF_BIF2 + j * 2 + 1] = b_ih2[51 + j]  + b_hh2[51 + j];
        sm[OFF_BGO2 + j * 2 + 0] = b_ih2[102 + j] + b_hh2[102 + j];
        sm[OFF_BGO2 + j * 2 + 1] = b_ih2[153 + j] + b_hh2[153 + j];
        sm[OFF_WLIN + j] = W_lin[j];
    }
    __syncthreads();

    // ---- thread mapping: warp-uniform chunk => broadcast weight loads ----
    const int chunk = tid >> 6;           // 0..3, uniform within a warp
    const int bl    = tid & 63;           // batch-local, consecutive per lane
    const int j0    = chunk * 13;
    const float blin = b_lin[0];

    float c1[13], c2[13];
#pragma unroll
    for (int jj = 0; jj < 13; jj++) { c1[jj] = 0.0f; c2[jj] = 0.0f; }

    const size_t growbase = (size_t)(blockIdx.x * BT) * TSEQ;

    const float* __restrict__ h1b = sm + OFF_H1 + bl * 2;   // [k][bl][2]
    const float* __restrict__ h2b = sm + OFF_H2 + bl * 2;

#pragma unroll 1
    for (int t0 = 0; t0 < TSEQ; t0 += 32) {
        // stage 64x32 input tile (coalesced)
#pragma unroll
        for (int rep = 0; rep < 8; rep++) {
            int idx = tid + rep * NTHR;
            int rb = idx >> 5, cc = idx & 31;
            sm[OFF_XS + rb * 33 + cc] = input[growbase + (size_t)rb * TSEQ + t0 + cc];
        }
        __syncthreads();

#pragma unroll 1
        for (int ti = 0; ti < 32; ti++) {
            const float xb = sm[OFF_XS + bl * 33 + ti];
            const u64 xdup = pack2(xb, xb);

            u64 aif[13], ago[13];

            // ======== layer 1 gates: acc = Wx*x + b + Whh*h1 ========
#pragma unroll
            for (int jj = 0; jj < 13; jj++) {
                int j = j0 + jj;
                aif[jj] = ffma2_o(*(const u64*)(sm + OFF_WXIF + j * 2), xdup,
                                  *(const u64*)(sm + OFF_BIF1 + j * 2));
                ago[jj] = ffma2_o(*(const u64*)(sm + OFF_WXGO + j * 2), xdup,
                                  *(const u64*)(sm + OFF_BGO1 + j * 2));
            }
#pragma unroll 2
            for (int k = 0; k < HP; k++) {
                const u64 hd = *(const u64*)(h1b + k * (BT * 2));
#pragma unroll
                for (int jj = 0; jj < 13; jj++) {
                    const ulonglong2 w = *(const ulonglong2*)(sm + OFF_W1 + (j0 + jj) * 208 + k * 4);
                    ffma2(aif[jj], w.x, hd);   // (i,f)
                    ffma2(ago[jj], w.y, hd);   // (g,o)
                }
            }
            __syncthreads();   // all reads of h1(prev) done

            // epilogue 1: write h1(new), duplicated
            {
                float* h1w = sm + OFF_H1 + bl * 2;
#pragma unroll
                for (int jj = 0; jj < 13; jj++) {
                    float ip, fp, gp, op;
                    unpack2(aif[jj], ip, fp);
                    unpack2(ago[jj], gp, op);
                    float cn = fmaf(fsig(fp), c1[jj], fsig(ip) * ftanh_(gp));
                    c1[jj] = cn;
                    float hv = fsig(op) * ftanh_(cn);
                    *(float2*)(h1w + (j0 + jj) * (BT * 2)) = make_float2(hv, hv);
                }
            }
            __syncthreads();   // h1(new) visible

            // ======== layer 2 gates: acc = b + Wih2*h1new + Whh2*h2 ========
#pragma unroll
            for (int jj = 0; jj < 13; jj++) {
                int j = j0 + jj;
                aif[jj] = *(const u64*)(sm + OFF_BIF2 + j * 2);
                ago[jj] = *(const u64*)(sm + OFF_BGO2 + j * 2);
            }
#pragma unroll 2
            for (int k = 0; k < HP; k++) {
                const u64 hd = *(const u64*)(h1b + k * (BT * 2));
#pragma unroll
                for (int jj = 0; jj < 13; jj++) {
                    const ulonglong2 w = *(const ulonglong2*)(sm + OFF_W2 + (j0 + jj) * 416 + k * 4);
                    ffma2(aif[jj], w.x, hd);
                    ffma2(ago[jj], w.y, hd);
                }
            }
#pragma unroll 2
            for (int k = 0; k < HP; k++) {
                const u64 hd = *(const u64*)(h2b + k * (BT * 2));
#pragma unroll
                for (int jj = 0; jj < 13; jj++) {
                    const ulonglong2 w = *(const ulonglong2*)(sm + OFF_W2 + (j0 + jj) * 416 + (52 + k) * 4);
                    ffma2(aif[jj], w.x, hd);
                    ffma2(ago[jj], w.y, hd);
                }
            }
            __syncthreads();   // all reads of h2(prev) done

            // epilogue 2: write h2(new) + partial output dot
            {
                float* h2w = sm + OFF_H2 + bl * 2;
                float s = 0.0f;
#pragma unroll
                for (int jj = 0; jj < 13; jj++) {
                    float ip, fp, gp, op;
                    unpack2(aif[jj], ip, fp);
                    unpack2(ago[jj], gp, op);
                    float cn = fmaf(fsig(fp), c2[jj], fsig(ip) * ftanh_(gp));
                    c2[jj] = cn;
                    float hv = fsig(op) * ftanh_(cn);
                    *(float2*)(h2w + (j0 + jj) * (BT * 2)) = make_float2(hv, hv);
                    s = fmaf(sm[OFF_WLIN + j0 + jj], hv, s);
                }
                sm[OFF_PART + chunk * BT + bl] = s;
            }
            __syncthreads();   // h2(new) + partials visible

            if (chunk == 0) {
                float o = blin
                        + sm[OFF_PART + bl] + sm[OFF_PART + BT + bl]
                        + sm[OFF_PART + 2 * BT + bl] + sm[OFF_PART + 3 * BT + bl];
                sm[OFF_OS + bl * 33 + ti] = o;
            }
        }
        __syncthreads();

        // flush 64x32 output tile (coalesced)
#pragma unroll
        for (int rep = 0; rep < 8; rep++) {
            int idx = tid + rep * NTHR;
            int rb = idx >> 5, cc = idx & 31;
            out[growbase + (size_t)rb * TSEQ + t0 + cc] = sm[OFF_OS + rb * 33 + cc];
        }
    }
}

extern "C" void kernel_launch(void* const* d_in, const int* in_sizes, int n_in,
                              void* d_out, int out_size) {
    const float* input = (const float*)d_in[0];
    const float* W_ih1 = (const float*)d_in[1];
    const float* W_hh1 = (const float*)d_in[2];
    const float* b_ih1 = (const float*)d_in[3];
    const float* b_hh1 = (const float*)d_in[4];
    const float* W_ih2 = (const float*)d_in[5];
    const float* W_hh2 = (const float*)d_in[6];
    const float* b_ih2 = (const float*)d_in[7];
    const float* b_hh2 = (const float*)d_in[8];
    const float* W_lin = (const float*)d_in[9];
    const float* b_lin = (const float*)d_in[10];
    float* out = (float*)d_out;

    const int B = in_sizes[0] / TSEQ;     // 8192
    const int grid = B / BT;              // 128 persistent CTAs

    cudaFuncSetAttribute(lstm_f32x2_kernel,
                         cudaFuncAttributeMaxDynamicSharedMemorySize, SMEM_BYTES);

    lstm_f32x2_kernel<<<grid, NTHR, SMEM_BYTES>>>(
        input, W_ih1, W_hh1, b_ih1, b_hh1,
        W_ih2, W_hh2, b_ih2, b_hh2, W_lin, b_lin, out);
}

// round 5
// speedup vs baseline: 1.0025x; 1.0025x over previous
#include <cuda_runtime.h>

#define TSEQ 2048
#define NTHR 256
#define BT   64

typedef unsigned long long u64;

// ---------------------------------------------------------------------------
// Packed f32x2 helpers (Blackwell). ptxas never auto-fuses FFMA2 from C++;
// it only exists via PTX fma.rn.f32x2.
// ---------------------------------------------------------------------------
__device__ __forceinline__ void ffma2(u64& d, u64 a, u64 b) {
    asm("fma.rn.f32x2 %0, %1, %2, %0;" : "+l"(d) : "l"(a), "l"(b));
}
__device__ __forceinline__ u64 ffma2_o(u64 a, u64 b, u64 c) {
    u64 d; asm("fma.rn.f32x2 %0, %1, %2, %3;" : "=l"(d) : "l"(a), "l"(b), "l"(c));
    return d;
}
__device__ __forceinline__ u64 pack2(float lo, float hi) {
    u64 r; asm("mov.b64 %0, {%1, %2};" : "=l"(r) : "f"(lo), "f"(hi)); return r;
}
__device__ __forceinline__ void unpack2(u64 v, float& lo, float& hi) {
    asm("mov.b64 {%0, %1}, %2;" : "=f"(lo), "=f"(hi) : "l"(v));
}

// Accurate-enough nonlinearities: ex2.approx + rcp.approx (~2 ulp each).
__device__ __forceinline__ float fsig(float x) {
    return __fdividef(1.0f, 1.0f + __expf(-x));
}
__device__ __forceinline__ float ftanh_(float x) {
    x = fminf(fmaxf(x, -15.0f), 15.0f);
    float e = __expf(-2.0f * x);
    return __fdividef(1.0f - e, 1.0f + e);
}

// ---------------------------------------------------------------------------
// SMEM layout (float indices). H=51 padded to HP=52 (padding zeroed).
// Weights interleaved [j][k][gate q=0..3] -> one LDS.128 = packed (i,f),(g,o).
// h stored DUPLICATED as [k][batch][2] -> one LDS.64 = dup'd h operand.
// ---------------------------------------------------------------------------
constexpr int HP = 52;

constexpr int OFF_W1   = 0;                         // [52][52][4]  = 10816
constexpr int OFF_W2   = OFF_W1 + 52 * 52 * 4;      // [52][104][4] = 21632
constexpr int OFF_WXIF = OFF_W2 + 52 * 104 * 4;     // [52][2]
constexpr int OFF_WXGO = OFF_WXIF + 104;
constexpr int OFF_BIF1 = OFF_WXGO + 104;
constexpr int OFF_BGO1 = OFF_BIF1 + 104;
constexpr int OFF_BIF2 = OFF_BGO1 + 104;
constexpr int OFF_BGO2 = OFF_BIF2 + 104;
constexpr int OFF_WLIN = OFF_BGO2 + 104;            // [52]
constexpr int OFF_H1   = OFF_WLIN + 52;             // [52][64][2] = 6656 (even ✓)
constexpr int OFF_H2   = OFF_H1 + 52 * BT * 2;      // 6656
constexpr int OFF_XS   = OFF_H2 + 52 * BT * 2;      // [64][33] = 2112
constexpr int OFF_OS   = OFF_XS + BT * 33;          // 2112
constexpr int OFF_PART = OFF_OS + BT * 33;          // [4][64]
constexpr int SMEM_FLOATS = OFF_PART + 4 * BT;
constexpr int SMEM_BYTES  = SMEM_FLOATS * 4;        // ~203.7 KB

__global__ void __launch_bounds__(NTHR, 1) lstm_f32x2_kernel(
    const float* __restrict__ input,
    const float* __restrict__ W_ih1, const float* __restrict__ W_hh1,
    const float* __restrict__ b_ih1, const float* __restrict__ b_hh1,
    const float* __restrict__ W_ih2, const float* __restrict__ W_hh2,
    const float* __restrict__ b_ih2, const float* __restrict__ b_hh2,
    const float* __restrict__ W_lin, const float* __restrict__ b_lin,
    float* __restrict__ out)
{
    extern __shared__ float sm[];
    const int tid = threadIdx.x;

    // ---- zero everything up to XS (weight padding + h/c state) ----
    for (int i = tid; i < OFF_XS; i += NTHR) sm[i] = 0.0f;
    __syncthreads();

    // ---- stage weights: gate-interleaved [j][k][q] ----
    for (int i = tid; i < 4 * 51 * 51; i += NTHR) {
        int q = i / (51 * 51), rem = i - q * 51 * 51;
        int j = rem / 51, c = rem - j * 51;
        float whh1 = W_hh1[(q * 51 + j) * 51 + c];
        float wih2 = W_ih2[(q * 51 + j) * 51 + c];
        float whh2 = W_hh2[(q * 51 + j) * 51 + c];
        sm[OFF_W1 + j * 208 + c * 4 + q]        = whh1;
        sm[OFF_W2 + j * 416 + c * 4 + q]        = wih2;
        sm[OFF_W2 + j * 416 + (52 + c) * 4 + q] = whh2;
    }
    for (int j = tid; j < 51; j += NTHR) {
        sm[OFF_WXIF + j * 2 + 0] = W_ih1[j];
        sm[OFF_WXIF + j * 2 + 1] = W_ih1[51 + j];
        sm[OFF_WXGO + j * 2 + 0] = W_ih1[102 + j];
        sm[OFF_WXGO + j * 2 + 1] = W_ih1[153 + j];
        sm[OFF_BIF1 + j * 2 + 0] = b_ih1[j]       + b_hh1[j];
        sm[OFF_BIF1 + j * 2 + 1] = b_ih1[51 + j]  + b_hh1[51 + j];
        sm[OFF_BGO1 + j * 2 + 0] = b_ih1[102 + j] + b_hh1[102 + j];
        sm[OFF_BGO1 + j * 2 + 1] = b_ih1[153 + j] + b_hh1[153 + j];
        sm[OFF_BIF2 + j * 2 + 0] = b_ih2[j]       + b_hh2[j];
        sm[OFF_BIF2 + j * 2 + 1] = b_ih2[51 + j]  + b_hh2[51 + j];
        sm[OFF_BGO2 + j * 2 + 0] = b_ih2[102 + j] + b_hh2[102 + j];
        sm[OFF_BGO2 + j * 2 + 1] = b_ih2[153 + j] + b_hh2[153 + j];
        sm[OFF_WLIN + j] = W_lin[j];
    }
    __syncthreads();

    // ---- thread mapping: warp-uniform chunk => broadcast weight loads ----
    const int chunk = tid >> 6;           // 0..3, uniform within a warp
    const int bl    = tid & 63;           // batch-local, consecutive per lane
    const int j0    = chunk * 13;
    const float blin = b_lin[0];

    float c1[13], c2[13];
#pragma unroll
    for (int jj = 0; jj < 13; jj++) { c1[jj] = 0.0f; c2[jj] = 0.0f; }

    const size_t growbase = (size_t)(blockIdx.x * BT) * TSEQ;

    const float* __restrict__ h1b = sm + OFF_H1 + bl * 2;   // [k][bl][2]
    const float* __restrict__ h2b = sm + OFF_H2 + bl * 2;

#pragma unroll 1
    for (int t0 = 0; t0 < TSEQ; t0 += 32) {
        // stage 64x32 input tile (coalesced)
#pragma unroll
        for (int rep = 0; rep < 8; rep++) {
            int idx = tid + rep * NTHR;
            int rb = idx >> 5, cc = idx & 31;
            sm[OFF_XS + rb * 33 + cc] = input[growbase + (size_t)rb * TSEQ + t0 + cc];
        }
        __syncthreads();

#pragma unroll 1
        for (int ti = 0; ti < 32; ti++) {
            const float xb = sm[OFF_XS + bl * 33 + ti];
            const u64 xdup = pack2(xb, xb);

            u64 aif[13], ago[13];

            // ======== layer 1 gates: acc = Wx*x + b + Whh*h1 ========
#pragma unroll
            for (int jj = 0; jj < 13; jj++) {
                int j = j0 + jj;
                aif[jj] = ffma2_o(*(const u64*)(sm + OFF_WXIF + j * 2), xdup,
                                  *(const u64*)(sm + OFF_BIF1 + j * 2));
                ago[jj] = ffma2_o(*(const u64*)(sm + OFF_WXGO + j * 2), xdup,
                                  *(const u64*)(sm + OFF_BGO1 + j * 2));
            }
#pragma unroll 2
            for (int k = 0; k < HP; k++) {
                const u64 hd = *(const u64*)(h1b + k * (BT * 2));
#pragma unroll
                for (int jj = 0; jj < 13; jj++) {
                    const ulonglong2 w = *(const ulonglong2*)(sm + OFF_W1 + (j0 + jj) * 208 + k * 4);
                    ffma2(aif[jj], w.x, hd);   // (i,f)
                    ffma2(ago[jj], w.y, hd);   // (g,o)
                }
            }
            __syncthreads();   // all reads of h1(prev) done

            // epilogue 1: write h1(new), duplicated
            {
                float* h1w = sm + OFF_H1 + bl * 2;
#pragma unroll
                for (int jj = 0; jj < 13; jj++) {
                    float ip, fp, gp, op;
                    unpack2(aif[jj], ip, fp);
                    unpack2(ago[jj], gp, op);
                    float cn = fmaf(fsig(fp), c1[jj], fsig(ip) * ftanh_(gp));
                    c1[jj] = cn;
                    float hv = fsig(op) * ftanh_(cn);
                    *(float2*)(h1w + (j0 + jj) * (BT * 2)) = make_float2(hv, hv);
                }
            }
            __syncthreads();   // h1(new) visible

            // ======== layer 2 gates: acc = b + Wih2*h1new + Whh2*h2 ========
#pragma unroll
            for (int jj = 0; jj < 13; jj++) {
                int j = j0 + jj;
                aif[jj] = *(const u64*)(sm + OFF_BIF2 + j * 2);
                ago[jj] = *(const u64*)(sm + OFF_BGO2 + j * 2);
            }
#pragma unroll 2
            for (int k = 0; k < HP; k++) {
                const u64 hd = *(const u64*)(h1b + k * (BT * 2));
#pragma unroll
                for (int jj = 0; jj < 13; jj++) {
                    const ulonglong2 w = *(const ulonglong2*)(sm + OFF_W2 + (j0 + jj) * 416 + k * 4);
                    ffma2(aif[jj], w.x, hd);
                    ffma2(ago[jj], w.y, hd);
                }
            }
#pragma unroll 2
            for (int k = 0; k < HP; k++) {
                const u64 hd = *(const u64*)(h2b + k * (BT * 2));
#pragma unroll
                for (int jj = 0; jj < 13; jj++) {
                    const ulonglong2 w = *(const ulonglong2*)(sm + OFF_W2 + (j0 + jj) * 416 + (52 + k) * 4);
                    ffma2(aif[jj], w.x, hd);
                    ffma2(ago[jj], w.y, hd);
                }
            }
            __syncthreads();   // all reads of h2(prev) done

            // epilogue 2: write h2(new) + partial output dot
            {
                float* h2w = sm + OFF_H2 + bl * 2;
                float s = 0.0f;
#pragma unroll
                for (int jj = 0; jj < 13; jj++) {
                    float ip, fp, gp, op;
                    unpack2(aif[jj], ip, fp);
                    unpack2(ago[jj], gp, op);
                    float cn = fmaf(fsig(fp), c2[jj], fsig(ip) * ftanh_(gp));
                    c2[jj] = cn;
                    float hv = fsig(op) * ftanh_(cn);
                    *(float2*)(h2w + (j0 + jj) * (BT * 2)) = make_float2(hv, hv);
                    s = fmaf(sm[OFF_WLIN + j0 + jj], hv, s);
                }
                sm[OFF_PART + chunk * BT + bl] = s;
            }
            __syncthreads();   // h2(new) + partials visible

            if (chunk == 0) {
                float o = blin
                        + sm[OFF_PART + bl] + sm[OFF_PART + BT + bl]
                        + sm[OFF_PART + 2 * BT + bl] + sm[OFF_PART + 3 * BT + bl];
                sm[OFF_OS + bl * 33 + ti] = o;
            }
        }
        __syncthreads();

        // flush 64x32 output tile (coalesced)
#pragma unroll
        for (int rep = 0; rep < 8; rep++) {
            int idx = tid + rep * NTHR;
            int rb = idx >> 5, cc = idx & 31;
            out[growbase + (size_t)rb * TSEQ + t0 + cc] = sm[OFF_OS + rb * 33 + cc];
        }
    }
}

extern "C" void kernel_launch(void* const* d_in, const int* in_sizes, int n_in,
                              void* d_out, int out_size) {
    const float* input = (const float*)d_in[0];
    const float* W_ih1 = (const float*)d_in[1];
    const float* W_hh1 = (const float*)d_in[2];
    const float* b_ih1 = (const float*)d_in[3];
    const float* b_hh1 = (const float*)d_in[4];
    const float* W_ih2 = (const float*)d_in[5];
    const float* W_hh2 = (const float*)d_in[6];
    const float* b_ih2 = (const float*)d_in[7];
    const float* b_hh2 = (const float*)d_in[8];
    const float* W_lin = (const float*)d_in[9];
    const float* b_lin = (const float*)d_in[10];
    float* out = (float*)d_out;

    const int B = in_sizes[0] / TSEQ;     // 8192
    const int grid = B / BT;              // 128 persistent CTAs

    cudaFuncSetAttribute(lstm_f32x2_kernel,
                         cudaFuncAttributeMaxDynamicSharedMemorySize, SMEM_BYTES);

    lstm_f32x2_kernel<<<grid, NTHR, SMEM_BYTES>>>(
        input, W_ih1, W_hh1, b_ih1, b_hh1,
        W_ih2, W_hh2, b_ih2, b_hh2, W_lin, b_lin, out);
}

// round 7
// speedup vs baseline: 2.3511x; 2.3452x over previous
#include <cuda_runtime.h>
#include <cuda_bf16.h>
#include <cstdint>

#define TT   2048
#define NTHR 128

// row strides in bf16 elems; (stride/2) mod 32 == 4  -> conflict-free fragment access
constexpr int KA  = 136;
constexpr int KB1 = 72;
constexpr int KB2 = 136;

constexpr uint32_t A_LO   = 16u * KA * 2;            // lo tile offset within warp A region
constexpr uint32_t A_WARP = 2u * A_LO;               // 8704 B per warp (hi + lo)
constexpr uint32_t B1H = 4u * A_WARP;                // 34816
constexpr uint32_t B1L = B1H + 208u * KB1 * 2;       // 64768
constexpr uint32_t B2H = B1L + 208u * KB1 * 2;       // 94720
constexpr uint32_t B2L = B2H + 208u * KB2 * 2;       // 151296
constexpr uint32_t SMEM_BYTES = B2L + 208u * KB2 * 2; // 207872

// m16n8k16 row.col bf16 HMMA, fp32 accumulate (baseline PTX, family-target safe)
__device__ __forceinline__ void mma4(float* d,
                                     uint32_t a0, uint32_t a1, uint32_t a2, uint32_t a3,
                                     uint32_t b0, uint32_t b1) {
    asm volatile(
        "mma.sync.aligned.m16n8k16.row.col.f32.bf16.bf16.f32 "
        "{%0,%1,%2,%3}, {%4,%5,%6,%7}, {%8,%9}, {%0,%1,%2,%3};"
        : "+f"(d[0]), "+f"(d[1]), "+f"(d[2]), "+f"(d[3])
        : "r"(a0), "r"(a1), "r"(a2), "r"(a3), "r"(b0), "r"(b1));
}

// precise activations (~2ulp): ex2.approx + rcp.approx
__device__ __forceinline__ float fsig(float x) {
    return __fdividef(1.0f, 1.0f + __expf(-x));
}
__device__ __forceinline__ float ftanh_(float x) {
    x = fminf(fmaxf(x, -15.0f), 15.0f);
    float e = __expf(-2.0f * x);
    return __fdividef(1.0f - e, 1.0f + e);
}
__device__ __forceinline__ void bsplit(float v, __nv_bfloat16& h, __nv_bfloat16& l) {
    h = __float2bfloat16(v);
    l = __float2bfloat16(v - __bfloat162float(h));
}

__global__ void __launch_bounds__(NTHR, 1) lstm_hmma_kernel(
    const float* __restrict__ input,
    const float* __restrict__ W_ih1, const float* __restrict__ W_hh1,
    const float* __restrict__ b_ih1, const float* __restrict__ b_hh1,
    const float* __restrict__ W_ih2, const float* __restrict__ W_hh2,
    const float* __restrict__ b_ih2, const float* __restrict__ b_hh2,
    const float* __restrict__ W_lin, const float* __restrict__ b_lin,
    float* __restrict__ out)
{
    extern __shared__ char smc[];
    const int tid  = threadIdx.x;
    const int warp = tid >> 5, lane = tid & 31;
    const int cc = lane & 3, gg = lane >> 2;

    // ---- zero all smem ----
    for (uint32_t i = tid * 16; i < SMEM_BYTES; i += NTHR * 16)
        *(uint4*)(smc + i) = make_uint4(0, 0, 0, 0);
    __syncthreads();

    // gate-row -> n mapping: i->2j, f->2j+1, g->104+2j, o->105+2j
    // ---- stage B1 [208][72] hi/lo: k0-50 Whh1, k52 bias1, k53 Wih1 ----
    for (int idx = tid; idx < 204 * 53; idx += NTHR) {
        int R = idx / 53, kk = idx - R * 53;
        int q = R / 51, j = R - q * 51;
        int n = (q < 2) ? (2 * j + q) : (104 + 2 * j + (q - 2));
        float v; int col;
        if (kk < 51)       { v = W_hh1[R * 51 + kk];      col = kk; }
        else if (kk == 51) { v = b_ih1[R] + b_hh1[R];     col = 52; }
        else               { v = W_ih1[R];                col = 53; }
        __nv_bfloat16 h, l; bsplit(v, h, l);
        *(__nv_bfloat16*)(smc + B1H + (n * KB1 + col) * 2) = h;
        *(__nv_bfloat16*)(smc + B1L + (n * KB1 + col) * 2) = l;
    }
    // ---- stage B2 [208][136] hi/lo: k0-50 Wih2, k52 bias2, k56-106 Whh2 ----
    for (int idx = tid; idx < 204 * 103; idx += NTHR) {
        int R = idx / 103, kk = idx - R * 103;
        int q = R / 51, j = R - q * 51;
        int n = (q < 2) ? (2 * j + q) : (104 + 2 * j + (q - 2));
        float v; int col;
        if (kk < 51)       { v = W_ih2[R * 51 + kk];        col = kk; }
        else if (kk == 51) { v = b_ih2[R] + b_hh2[R];       col = 52; }
        else               { v = W_hh2[R * 51 + (kk - 52)]; col = 56 + (kk - 52); }
        __nv_bfloat16 h, l; bsplit(v, h, l);
        *(__nv_bfloat16*)(smc + B2H + (n * KB2 + col) * 2) = h;
        *(__nv_bfloat16*)(smc + B2L + (n * KB2 + col) * 2) = l;
    }
    // ---- A init: constant-one col 52 (hi), x(0) col 53 (hi+lo) ----
    if (tid < 64) {
        int w = tid >> 4, rl = tid & 15;
        uint32_t ab = w * A_WARP;
        *(__nv_bfloat16*)(smc + ab + (rl * KA + 52) * 2) = __float2bfloat16(1.0f);
        float x0 = input[((long)blockIdx.x * 64 + tid) * TT];
        __nv_bfloat16 h, l; bsplit(x0, h, l);
        *(__nv_bfloat16*)(smc + ab +        (rl * KA + 53) * 2) = h;
        *(__nv_bfloat16*)(smc + ab + A_LO + (rl * KA + 53) * 2) = l;
    }
    __syncthreads();

    // ---- per-thread fragment bases (byte offsets) ----
    const uint32_t aH   = warp * A_WARP + (gg * KA + 2 * cc) * 2;
    const uint32_t aL   = aH + A_LO;
    const uint32_t b1h  = B1H + (gg * KB1 + 2 * cc) * 2;
    const uint32_t b1l  = B1L + (gg * KB1 + 2 * cc) * 2;
    const uint32_t b2h  = B2H + (gg * KB2 + 2 * cc) * 2;
    const uint32_t b2l  = B2L + (gg * KB2 + 2 * cc) * 2;
    const uint32_t whA  = warp * A_WARP + (gg * KA) * 2;   // h-write base, row gg

    float wl[13];
#pragma unroll
    for (int q = 0; q < 13; q++) { int j = 4 * q + cc; wl[q] = (j < 51) ? W_lin[j] : 0.f; }
    const float blin = b_lin[0];

    float c1a[13], c1b[13], c2a[13], c2b[13];
#pragma unroll
    for (int q = 0; q < 13; q++) { c1a[q] = c1b[q] = c2a[q] = c2b[q] = 0.f; }

    const long rg0 = (long)blockIdx.x * 64 + warp * 16 + gg;   // D rows: rg0, rg0+8

    float D[26][4];

#pragma unroll 1
    for (int t = 0; t < TT; t++) {
        // prefetch x(t+1)
        float xn0 = 0.f, xn1 = 0.f;
        if (cc == 0 && t + 1 < TT) {
            xn0 = input[rg0 * TT + t + 1];
            xn1 = input[(rg0 + 8) * TT + t + 1];
        }

        // ================= layer 1 MMA: ksteps 0-3 (A cols 0-63) =================
#pragma unroll
        for (int nt = 0; nt < 26; nt++) { D[nt][0] = 0.f; D[nt][1] = 0.f; D[nt][2] = 0.f; D[nt][3] = 0.f; }
#pragma unroll
        for (int ks = 0; ks < 4; ks++) {
            const uint32_t ah0 = *(const uint32_t*)(smc + aH + ks * 32);
            const uint32_t ah1 = *(const uint32_t*)(smc + aH + 2176 + ks * 32);
            const uint32_t ah2 = *(const uint32_t*)(smc + aH + 16 + ks * 32);
            const uint32_t ah3 = *(const uint32_t*)(smc + aH + 2192 + ks * 32);
            const uint32_t al0 = *(const uint32_t*)(smc + aL + ks * 32);
            const uint32_t al1 = *(const uint32_t*)(smc + aL + 2176 + ks * 32);
            const uint32_t al2 = *(const uint32_t*)(smc + aL + 16 + ks * 32);
            const uint32_t al3 = *(const uint32_t*)(smc + aL + 2192 + ks * 32);
#pragma unroll
            for (int nt = 0; nt < 26; nt++) {
                const uint32_t bo = nt * 1152 + ks * 32;
                const uint32_t bh0 = *(const uint32_t*)(smc + b1h + bo);
                const uint32_t bh1 = *(const uint32_t*)(smc + b1h + bo + 16);
                mma4(D[nt], ah0, ah1, ah2, ah3, bh0, bh1);
                mma4(D[nt], al0, al1, al2, al3, bh0, bh1);
                const uint32_t bl0 = *(const uint32_t*)(smc + b1l + bo);
                const uint32_t bl1 = *(const uint32_t*)(smc + b1l + bo + 16);
                mma4(D[nt], ah0, ah1, ah2, ah3, bl0, bl1);
            }
        }

        // ================= epilogue 1: c1/h1, write h1 to A cols j =================
#pragma unroll
        for (int q = 0; q < 13; q++) {
            float i0 = D[q][0], f0 = D[q][1], i1 = D[q][2], f1 = D[q][3];
            float g0 = D[13 + q][0], o0 = D[13 + q][1], g1 = D[13 + q][2], o1 = D[13 + q][3];
            float cn0 = fmaf(fsig(f0), c1a[q], fsig(i0) * ftanh_(g0));
            float cn1 = fmaf(fsig(f1), c1b[q], fsig(i1) * ftanh_(g1));
            c1a[q] = cn0; c1b[q] = cn1;
            float h0 = fsig(o0) * ftanh_(cn0);
            float h1v = fsig(o1) * ftanh_(cn1);
            const int j2 = (4 * q + cc) * 2;
            __nv_bfloat16 bh, bl;
            bsplit(h0, bh, bl);
            *(__nv_bfloat16*)(smc + whA + j2)        = bh;
            *(__nv_bfloat16*)(smc + whA + A_LO + j2) = bl;
            bsplit(h1v, bh, bl);
            *(__nv_bfloat16*)(smc + whA + 2176 + j2)        = bh;
            *(__nv_bfloat16*)(smc + whA + A_LO + 2176 + j2) = bl;
        }
        __syncwarp();

        // ================= layer 2 MMA: ksteps 0-6 (A cols 0-111) =================
#pragma unroll
        for (int nt = 0; nt < 26; nt++) { D[nt][0] = 0.f; D[nt][1] = 0.f; D[nt][2] = 0.f; D[nt][3] = 0.f; }
#pragma unroll
        for (int ks = 0; ks < 7; ks++) {
            const uint32_t ah0 = *(const uint32_t*)(smc + aH + ks * 32);
            const uint32_t ah1 = *(const uint32_t*)(smc + aH + 2176 + ks * 32);
            const uint32_t ah2 = *(const uint32_t*)(smc + aH + 16 + ks * 32);
            const uint32_t ah3 = *(const uint32_t*)(smc + aH + 2192 + ks * 32);
            const uint32_t al0 = *(const uint32_t*)(smc + aL + ks * 32);
            const uint32_t al1 = *(const uint32_t*)(smc + aL + 2176 + ks * 32);
            const uint32_t al2 = *(const uint32_t*)(smc + aL + 16 + ks * 32);
            const uint32_t al3 = *(const uint32_t*)(smc + aL + 2192 + ks * 32);
#pragma unroll
            for (int nt = 0; nt < 26; nt++) {
                const uint32_t bo = nt * 2176 + ks * 32;
                const uint32_t bh0 = *(const uint32_t*)(smc + b2h + bo);
                const uint32_t bh1 = *(const uint32_t*)(smc + b2h + bo + 16);
                mma4(D[nt], ah0, ah1, ah2, ah3, bh0, bh1);
                mma4(D[nt], al0, al1, al2, al3, bh0, bh1);
                const uint32_t bl0 = *(const uint32_t*)(smc + b2l + bo);
                const uint32_t bl1 = *(const uint32_t*)(smc + b2l + bo + 16);
                mma4(D[nt], ah0, ah1, ah2, ah3, bl0, bl1);
            }
        }

        // ========= epilogue 2: c2/h2, write h2 to A cols 56+j, out proj =========
        float s0 = 0.f, s1 = 0.f;
#pragma unroll
        for (int q = 0; q < 13; q++) {
            float i0 = D[q][0], f0 = D[q][1], i1 = D[q][2], f1 = D[q][3];
            float g0 = D[13 + q][0], o0 = D[13 + q][1], g1 = D[13 + q][2], o1 = D[13 + q][3];
            float cn0 = fmaf(fsig(f0), c2a[q], fsig(i0) * ftanh_(g0));
            float cn1 = fmaf(fsig(f1), c2b[q], fsig(i1) * ftanh_(g1));
            c2a[q] = cn0; c2b[q] = cn1;
            float h0 = fsig(o0) * ftanh_(cn0);
            float h1v = fsig(o1) * ftanh_(cn1);
            s0 = fmaf(wl[q], h0, s0);
            s1 = fmaf(wl[q], h1v, s1);
            const int j2 = (56 + 4 * q + cc) * 2;
            __nv_bfloat16 bh, bl;
            bsplit(h0, bh, bl);
            *(__nv_bfloat16*)(smc + whA + j2)        = bh;
            *(__nv_bfloat16*)(smc + whA + A_LO + j2) = bl;
            bsplit(h1v, bh, bl);
            *(__nv_bfloat16*)(smc + whA + 2176 + j2)        = bh;
            *(__nv_bfloat16*)(smc + whA + A_LO + 2176 + j2) = bl;
        }
        // stage x(t+1) into col 53
        if (cc == 0) {
            __nv_bfloat16 bh, bl;
            bsplit(xn0, bh, bl);
            *(__nv_bfloat16*)(smc + whA + 53 * 2)        = bh;
            *(__nv_bfloat16*)(smc + whA + A_LO + 53 * 2) = bl;
            bsplit(xn1, bh, bl);
            *(__nv_bfloat16*)(smc + whA + 2176 + 53 * 2)        = bh;
            *(__nv_bfloat16*)(smc + whA + A_LO + 2176 + 53 * 2) = bl;
        }
        // quad-reduce output dot, write
        s0 += __shfl_xor_sync(0xffffffffu, s0, 1);
        s0 += __shfl_xor_sync(0xffffffffu, s0, 2);
        s1 += __shfl_xor_sync(0xffffffffu, s1, 1);
        s1 += __shfl_xor_sync(0xffffffffu, s1, 2);
        if (cc == 0) {
            out[rg0 * TT + t]       = s0 + blin;
            out[(rg0 + 8) * TT + t] = s1 + blin;
        }
        __syncwarp();
    }
}

extern "C" void kernel_launch(void* const* d_in, const int* in_sizes, int n_in,
                              void* d_out, int out_size) {
    const float* input = (const float*)d_in[0];
    const float* W_ih1 = (const float*)d_in[1];
    const float* W_hh1 = (const float*)d_in[2];
    const float* b_ih1 = (const float*)d_in[3];
    const float* b_hh1 = (const float*)d_in[4];
    const float* W_ih2 = (const float*)d_in[5];
    const float* W_hh2 = (const float*)d_in[6];
    const float* b_ih2 = (const float*)d_in[7];
    const float* b_hh2 = (const float*)d_in[8];
    const float* W_lin = (const float*)d_in[9];
    const float* b_lin = (const float*)d_in[10];
    float* out = (float*)d_out;

    const int B = in_sizes[0] / TT;        // 8192
    const int grid = B / 64;               // 128 persistent CTAs (64 rows each)

    cudaFuncSetAttribute(lstm_hmma_kernel,
                         cudaFuncAttributeMaxDynamicSharedMemorySize, SMEM_BYTES);

    lstm_hmma_kernel<<<grid, NTHR, SMEM_BYTES>>>(
        input, W_ih1, W_hh1, b_ih1, b_hh1,
        W_ih2, W_hh2, b_ih2, b_hh2, W_lin, b_lin, out);
}

// round 8
// speedup vs baseline: 2.9740x; 1.2649x over previous
#include <cuda_runtime.h>
#include <cuda_bf16.h>
#include <cstdint>

#define TT   2048
#define NTHR 256

// row strides in bf16 elems; (stride/2) mod 32 == 4 -> conflict-free fragment access
constexpr int KA  = 136;
constexpr int KB1 = 72;
constexpr int KB2 = 136;

constexpr uint32_t A_LO   = 16u * KA * 2;             // lo tile offset within pair A region
constexpr uint32_t A_WARP = 2u * A_LO;                // 8704 B per pair (hi + lo)
constexpr uint32_t B1H = 4u * A_WARP;                 // 34816
constexpr uint32_t B1L = B1H + 208u * KB1 * 2;
constexpr uint32_t B2H = B1L + 208u * KB1 * 2;
constexpr uint32_t B2L = B2H + 208u * KB2 * 2;
constexpr uint32_t SCRATCH = B2L + 208u * KB2 * 2;    // 207872: [4 pair][2 role][16 row] f32
constexpr uint32_t SMEM_BYTES = SCRATCH + 512;        // 208384

// m16n8k16 row.col bf16 HMMA, fp32 accumulate (family-target safe)
__device__ __forceinline__ void mma4(float* d,
                                     uint32_t a0, uint32_t a1, uint32_t a2, uint32_t a3,
                                     uint32_t b0, uint32_t b1) {
    asm volatile(
        "mma.sync.aligned.m16n8k16.row.col.f32.bf16.bf16.f32 "
        "{%0,%1,%2,%3}, {%4,%5,%6,%7}, {%8,%9}, {%0,%1,%2,%3};"
        : "+f"(d[0]), "+f"(d[1]), "+f"(d[2]), "+f"(d[3])
        : "r"(a0), "r"(a1), "r"(a2), "r"(a3), "r"(b0), "r"(b1));
}

__device__ __forceinline__ void pairbar(int pair) {
    asm volatile("bar.sync %0, 64;" :: "r"(pair + 1) : "memory");
}

// precise activations (~2ulp): ex2.approx + rcp.approx
__device__ __forceinline__ float fsig(float x) {
    return __fdividef(1.0f, 1.0f + __expf(-x));
}
__device__ __forceinline__ float ftanh_(float x) {
    x = fminf(fmaxf(x, -15.0f), 15.0f);
    float e = __expf(-2.0f * x);
    return __fdividef(1.0f - e, 1.0f + e);
}
__device__ __forceinline__ void bsplit(float v, __nv_bfloat16& h, __nv_bfloat16& l) {
    h = __float2bfloat16(v);
    l = __float2bfloat16(v - __bfloat162float(h));
}

__global__ void __launch_bounds__(NTHR, 1) lstm_hmma2_kernel(
    const float* __restrict__ input,
    const float* __restrict__ W_ih1, const float* __restrict__ W_hh1,
    const float* __restrict__ b_ih1, const float* __restrict__ b_hh1,
    const float* __restrict__ W_ih2, const float* __restrict__ W_hh2,
    const float* __restrict__ b_ih2, const float* __restrict__ b_hh2,
    const float* __restrict__ W_lin, const float* __restrict__ b_lin,
    float* __restrict__ out)
{
    extern __shared__ char smc[];
    const int tid  = threadIdx.x;
    const int warp = tid >> 5, lane = tid & 31;
    const int pair = warp >> 1, role = warp & 1;
    const int cc = lane & 3, gg = lane >> 2;

    // ---- zero all smem ----
    for (uint32_t i = tid * 16; i < SMEM_BYTES; i += NTHR * 16)
        *(uint4*)(smc + i) = make_uint4(0, 0, 0, 0);
    __syncthreads();

    // gate-row -> n mapping: i->2j, f->2j+1, g->104+2j, o->105+2j
    // ---- stage B1 [208][72] hi/lo: k0-50 Whh1, k52 bias1, k53 Wih1 ----
    for (int idx = tid; idx < 204 * 53; idx += NTHR) {
        int R = idx / 53, kk = idx - R * 53;
        int q = R / 51, j = R - q * 51;
        int n = (q < 2) ? (2 * j + q) : (104 + 2 * j + (q - 2));
        float v; int col;
        if (kk < 51)       { v = W_hh1[R * 51 + kk];      col = kk; }
        else if (kk == 51) { v = b_ih1[R] + b_hh1[R];     col = 52; }
        else               { v = W_ih1[R];                col = 53; }
        __nv_bfloat16 h, l; bsplit(v, h, l);
        *(__nv_bfloat16*)(smc + B1H + (n * KB1 + col) * 2) = h;
        *(__nv_bfloat16*)(smc + B1L + (n * KB1 + col) * 2) = l;
    }
    // ---- stage B2 [208][136] hi/lo: k0-50 Wih2, k52 bias2, k56-106 Whh2 ----
    for (int idx = tid; idx < 204 * 103; idx += NTHR) {
        int R = idx / 103, kk = idx - R * 103;
        int q = R / 51, j = R - q * 51;
        int n = (q < 2) ? (2 * j + q) : (104 + 2 * j + (q - 2));
        float v; int col;
        if (kk < 51)       { v = W_ih2[R * 51 + kk];        col = kk; }
        else if (kk == 51) { v = b_ih2[R] + b_hh2[R];       col = 52; }
        else               { v = W_hh2[R * 51 + (kk - 52)]; col = 56 + (kk - 52); }
        __nv_bfloat16 h, l; bsplit(v, h, l);
        *(__nv_bfloat16*)(smc + B2H + (n * KB2 + col) * 2) = h;
        *(__nv_bfloat16*)(smc + B2L + (n * KB2 + col) * 2) = l;
    }
    // ---- A init: constant-one col 52 (hi), x(0) col 53 (hi+lo) ----
    if (tid < 64) {
        int p = tid >> 4, rl = tid & 15;
        uint32_t ab = p * A_WARP;
        *(__nv_bfloat16*)(smc + ab + (rl * KA + 52) * 2) = __float2bfloat16(1.0f);
        float x0 = input[((long)blockIdx.x * 64 + tid) * TT];
        __nv_bfloat16 h, l; bsplit(x0, h, l);
        *(__nv_bfloat16*)(smc + ab +        (rl * KA + 53) * 2) = h;
        *(__nv_bfloat16*)(smc + ab + A_LO + (rl * KA + 53) * 2) = l;
    }
    __syncthreads();

    // ---- per-thread fragment bases ----
    const uint32_t aH  = pair * A_WARP + (gg * KA + 2 * cc) * 2;
    const uint32_t aL  = aH + A_LO;
    const uint32_t b1h = B1H + (gg * KB1 + 2 * cc) * 2;
    const uint32_t b1l = B1L + (gg * KB1 + 2 * cc) * 2;
    const uint32_t b2h = B2H + (gg * KB2 + 2 * cc) * 2;
    const uint32_t b2l = B2L + (gg * KB2 + 2 * cc) * 2;
    const uint32_t whA = pair * A_WARP + (gg * KA) * 2;    // h-write base, row gg
    float* const scr   = (float*)(smc + SCRATCH);

    // gate-tile split: role0 -> jt 0..6, role1 -> jt 6..12 (tile 6 duplicated)
    const int jt0 = role ? 6 : 0;

    float wl[7];
#pragma unroll
    for (int q = 0; q < 7; q++) {
        int j = 4 * (jt0 + q) + cc;
        wl[q] = (j < 51) ? W_lin[j] : 0.f;
    }
    if (role == 1) wl[0] = 0.f;   // jt6 counted by role0
    const float blin = b_lin[0];

    float c1a[7], c1b[7], c2a[7], c2b[7];
#pragma unroll
    for (int q = 0; q < 7; q++) { c1a[q] = c1b[q] = c2a[q] = c2b[q] = 0.f; }

    const long rg0 = (long)blockIdx.x * 64 + pair * 16 + gg;   // D rows: rg0, rg0+8

    float D[14][4];

#pragma unroll 1
    for (int t = 0; t < TT; t++) {
        // prefetch x(t+1) (role1 stages x)
        float xn0 = 0.f, xn1 = 0.f;
        if (role == 1 && cc == 0 && t + 1 < TT) {
            xn0 = input[rg0 * TT + t + 1];
            xn1 = input[(rg0 + 8) * TT + t + 1];
        }

        // ================= layer 1 MMA: ks 0-3 (A cols 0-63) =================
#pragma unroll
        for (int nt = 0; nt < 14; nt++) { D[nt][0] = 0.f; D[nt][1] = 0.f; D[nt][2] = 0.f; D[nt][3] = 0.f; }
#pragma unroll
        for (int ks = 0; ks < 4; ks++) {
            const uint32_t ah0 = *(const uint32_t*)(smc + aH + ks * 32);
            const uint32_t ah1 = *(const uint32_t*)(smc + aH + 2176 + ks * 32);
            const uint32_t ah2 = *(const uint32_t*)(smc + aH + 16 + ks * 32);
            const uint32_t ah3 = *(const uint32_t*)(smc + aH + 2192 + ks * 32);
            const uint32_t al0 = *(const uint32_t*)(smc + aL + ks * 32);
            const uint32_t al1 = *(const uint32_t*)(smc + aL + 2176 + ks * 32);
            const uint32_t al2 = *(const uint32_t*)(smc + aL + 16 + ks * 32);
            const uint32_t al3 = *(const uint32_t*)(smc + aL + 2192 + ks * 32);
#pragma unroll
            for (int q = 0; q < 7; q++) {
                const uint32_t boI = (uint32_t)(jt0 + q) * 1152 + ks * 32;        // i/f tile
                const uint32_t boG = (uint32_t)(13 + jt0 + q) * 1152 + ks * 32;   // g/o tile
                uint32_t bh0 = *(const uint32_t*)(smc + b1h + boI);
                uint32_t bh1 = *(const uint32_t*)(smc + b1h + boI + 16);
                mma4(D[q], ah0, ah1, ah2, ah3, bh0, bh1);
                mma4(D[q], al0, al1, al2, al3, bh0, bh1);
                uint32_t bl0 = *(const uint32_t*)(smc + b1l + boI);
                uint32_t bl1 = *(const uint32_t*)(smc + b1l + boI + 16);
                mma4(D[q], ah0, ah1, ah2, ah3, bl0, bl1);
                bh0 = *(const uint32_t*)(smc + b1h + boG);
                bh1 = *(const uint32_t*)(smc + b1h + boG + 16);
                mma4(D[7 + q], ah0, ah1, ah2, ah3, bh0, bh1);
                mma4(D[7 + q], al0, al1, al2, al3, bh0, bh1);
                bl0 = *(const uint32_t*)(smc + b1l + boG);
                bl1 = *(const uint32_t*)(smc + b1l + boG + 16);
                mma4(D[7 + q], ah0, ah1, ah2, ah3, bl0, bl1);
            }
        }
        pairbar(pair);   // MMA1 reads done before h1 overwrite

        // ================= epilogue 1: c1/h1, write h1 cols j =================
#pragma unroll
        for (int q = 0; q < 7; q++) {
            float i0 = D[q][0], f0 = D[q][1], i1 = D[q][2], f1 = D[q][3];
            float g0 = D[7 + q][0], o0 = D[7 + q][1], g1 = D[7 + q][2], o1 = D[7 + q][3];
            float cn0 = fmaf(fsig(f0), c1a[q], fsig(i0) * ftanh_(g0));
            float cn1 = fmaf(fsig(f1), c1b[q], fsig(i1) * ftanh_(g1));
            c1a[q] = cn0; c1b[q] = cn1;
            float h0  = fsig(o0) * ftanh_(cn0);
            float h1v = fsig(o1) * ftanh_(cn1);
            const int j2 = (4 * (jt0 + q) + cc) * 2;
            __nv_bfloat16 bh, bl;
            bsplit(h0, bh, bl);
            *(__nv_bfloat16*)(smc + whA + j2)        = bh;
            *(__nv_bfloat16*)(smc + whA + A_LO + j2) = bl;
            bsplit(h1v, bh, bl);
            *(__nv_bfloat16*)(smc + whA + 2176 + j2)        = bh;
            *(__nv_bfloat16*)(smc + whA + A_LO + 2176 + j2) = bl;
        }
        pairbar(pair);   // h1(t) visible to both warps

        // ================= layer 2 MMA: ks 0-6 (A cols 0-111) =================
#pragma unroll
        for (int nt = 0; nt < 14; nt++) { D[nt][0] = 0.f; D[nt][1] = 0.f; D[nt][2] = 0.f; D[nt][3] = 0.f; }
#pragma unroll
        for (int ks = 0; ks < 7; ks++) {
            const uint32_t ah0 = *(const uint32_t*)(smc + aH + ks * 32);
            const uint32_t ah1 = *(const uint32_t*)(smc + aH + 2176 + ks * 32);
            const uint32_t ah2 = *(const uint32_t*)(smc + aH + 16 + ks * 32);
            const uint32_t ah3 = *(const uint32_t*)(smc + aH + 2192 + ks * 32);
            const uint32_t al0 = *(const uint32_t*)(smc + aL + ks * 32);
            const uint32_t al1 = *(const uint32_t*)(smc + aL + 2176 + ks * 32);
            const uint32_t al2 = *(const uint32_t*)(smc + aL + 16 + ks * 32);
            const uint32_t al3 = *(const uint32_t*)(smc + aL + 2192 + ks * 32);
#pragma unroll
            for (int q = 0; q < 7; q++) {
                const uint32_t boI = (uint32_t)(jt0 + q) * 2176 + ks * 32;
                const uint32_t boG = (uint32_t)(13 + jt0 + q) * 2176 + ks * 32;
                uint32_t bh0 = *(const uint32_t*)(smc + b2h + boI);
                uint32_t bh1 = *(const uint32_t*)(smc + b2h + boI + 16);
                mma4(D[q], ah0, ah1, ah2, ah3, bh0, bh1);
                mma4(D[q], al0, al1, al2, al3, bh0, bh1);
                uint32_t bl0 = *(const uint32_t*)(smc + b2l + boI);
                uint32_t bl1 = *(const uint32_t*)(smc + b2l + boI + 16);
                mma4(D[q], ah0, ah1, ah2, ah3, bl0, bl1);
                bh0 = *(const uint32_t*)(smc + b2h + boG);
                bh1 = *(const uint32_t*)(smc + b2h + boG + 16);
                mma4(D[7 + q], ah0, ah1, ah2, ah3, bh0, bh1);
                mma4(D[7 + q], al0, al1, al2, al3, bh0, bh1);
                bl0 = *(const uint32_t*)(smc + b2l + boG);
                bl1 = *(const uint32_t*)(smc + b2l + boG + 16);
                mma4(D[7 + q], ah0, ah1, ah2, ah3, bl0, bl1);
            }
        }
        pairbar(pair);   // MMA2 reads done before h2 overwrite

        // ========= epilogue 2: c2/h2, write h2 cols 56+j, partial out =========
        float s0 = 0.f, s1 = 0.f;
#pragma unroll
        for (int q = 0; q < 7; q++) {
            float i0 = D[q][0], f0 = D[q][1], i1 = D[q][2], f1 = D[q][3];
            float g0 = D[7 + q][0], o0 = D[7 + q][1], g1 = D[7 + q][2], o1 = D[7 + q][3];
            float cn0 = fmaf(fsig(f0), c2a[q], fsig(i0) * ftanh_(g0));
            float cn1 = fmaf(fsig(f1), c2b[q], fsig(i1) * ftanh_(g1));
            c2a[q] = cn0; c2b[q] = cn1;
            float h0  = fsig(o0) * ftanh_(cn0);
            float h1v = fsig(o1) * ftanh_(cn1);
            s0 = fmaf(wl[q], h0, s0);
            s1 = fmaf(wl[q], h1v, s1);
            const int j2 = (56 + 4 * (jt0 + q) + cc) * 2;
            __nv_bfloat16 bh, bl;
            bsplit(h0, bh, bl);
            *(__nv_bfloat16*)(smc + whA + j2)        = bh;
            *(__nv_bfloat16*)(smc + whA + A_LO + j2) = bl;
            bsplit(h1v, bh, bl);
            *(__nv_bfloat16*)(smc + whA + 2176 + j2)        = bh;
            *(__nv_bfloat16*)(smc + whA + A_LO + 2176 + j2) = bl;
        }
        // quad-reduce partial, stash to scratch; role1 stages x(t+1)
        s0 += __shfl_xor_sync(0xffffffffu, s0, 1);
        s0 += __shfl_xor_sync(0xffffffffu, s0, 2);
        s1 += __shfl_xor_sync(0xffffffffu, s1, 1);
        s1 += __shfl_xor_sync(0xffffffffu, s1, 2);
        if (cc == 0) {
            scr[(pair * 2 + role) * 16 + gg]     = s0;
            scr[(pair * 2 + role) * 16 + 8 + gg] = s1;
            if (role == 1) {
                __nv_bfloat16 bh, bl;
                bsplit(xn0, bh, bl);
                *(__nv_bfloat16*)(smc + whA + 53 * 2)        = bh;
                *(__nv_bfloat16*)(smc + whA + A_LO + 53 * 2) = bl;
                bsplit(xn1, bh, bl);
                *(__nv_bfloat16*)(smc + whA + 2176 + 53 * 2)        = bh;
                *(__nv_bfloat16*)(smc + whA + A_LO + 2176 + 53 * 2) = bl;
            }
        }
        pairbar(pair);   // h2(t), x(t+1), partials visible

        if (role == 0 && cc == 0) {
            out[rg0 * TT + t]       = blin + scr[pair * 32 + gg]     + scr[pair * 32 + 16 + gg];
            out[(rg0 + 8) * TT + t] = blin + scr[pair * 32 + 8 + gg] + scr[pair * 32 + 24 + gg];
        }
    }
}

extern "C" void kernel_launch(void* const* d_in, const int* in_sizes, int n_in,
                              void* d_out, int out_size) {
    const float* input = (const float*)d_in[0];
    const float* W_ih1 = (const float*)d_in[1];
    const float* W_hh1 = (const float*)d_in[2];
    const float* b_ih1 = (const float*)d_in[3];
    const float* b_hh1 = (const float*)d_in[4];
    const float* W_ih2 = (const float*)d_in[5];
    const float* W_hh2 = (const float*)d_in[6];
    const float* b_ih2 = (const float*)d_in[7];
    const float* b_hh2 = (const float*)d_in[8];
    const float* W_lin = (const float*)d_in[9];
    const float* b_lin = (const float*)d_in[10];
    float* out = (float*)d_out;

    const int B = in_sizes[0] / TT;        // 8192
    const int grid = B / 64;               // 128 persistent CTAs (64 rows each)

    cudaFuncSetAttribute(lstm_hmma2_kernel,
                         cudaFuncAttributeMaxDynamicSharedMemorySize, SMEM_BYTES);

    lstm_hmma2_kernel<<<grid, NTHR, SMEM_BYTES>>>(
        input, W_ih1, W_hh1, b_ih1, b_hh1,
        W_ih2, W_hh2, b_ih2, b_hh2, W_lin, b_lin, out);
}